// round 9
// baseline (speedup 1.0000x reference)
#include <cuda_runtime.h>

#define NB     16
#define NCLS   20
#define NPM    27280          // anchors per modality
#define NPB    (2*NPM)        // 54560 anchors per batch
#define TOTAL  (NB*NPB)       // 872960
#define MAXD   1000
#define NPAD   1024           // padded detections (16 x 64)
#define MASKW  16             // 1024 bits -> 16 u64 words
#define TOPN   (NB*MAXD)      // 16000
#define HBINS  8192
#define BINOFF 121856         // (0x3F800000>>13) - 8192
#define CAP    4096           // candidate capacity per batch (fine bins -> C~1100)

typedef unsigned long long u64;

// Exact midpoint between 0.6f and nextafterf(0.6f, +inf).
// fl(inter/denom) > 0.6f  <=>  inter > MID*denom  (denom>0, RNE ties->0.6f fail '>')
#define IOU_MID 0.60000005364418029785156250

struct Ptrs { const float* p[30]; };

// ---- static device scratch (no allocations; statics zero-init) ----
__device__ unsigned int g_scores[TOTAL];
__device__ int          g_hist[NB*HBINS];     // re-zeroed inside k_compact each run
__device__ int          g_thr[NB];
__device__ int          g_ccount[NB];         // re-zeroed inside k_gather_maxoff
__device__ u64          g_cand[NB*CAP];
__device__ u64          g_topkeys[TOPN];
__device__ float        g_top_s[TOPN];
__device__ int          g_top_c[TOPN];
__device__ float        g_top_b[TOPN*4];
__device__ unsigned char g_valid[TOPN];
__device__ float        g_ob[TOPN*4];
__device__ float        g_area[TOPN];
__device__ u64          g_mask[(size_t)NB*NPAD*MASKW];

// sigmoid exactly as passing rounds (rel_err 1.3e-8) — do not change
__device__ __forceinline__ float sigm(float x){
    return __fdiv_rn(1.0f, __fadd_rn(1.0f, expf(-x)));
}

// monotone fine-grained score binning
__device__ __forceinline__ int score_bin(unsigned int bits){
    int v = (int)(bits >> 13) - BINOFF;
    return max(0, min(HBINS-1, v));
}

__device__ __forceinline__ void locate(int m, int& lvl, int& pos, int& w, int& st, int& hw){
    if (m < 20480)      { lvl=0; pos=m;        w=160; st=8;   hw=20480; }
    else if (m < 25600) { lvl=1; pos=m-20480;  w=80;  st=16;  hw=5120;  }
    else if (m < 26880) { lvl=2; pos=m-25600;  w=40;  st=32;  hw=1280;  }
    else if (m < 27200) { lvl=3; pos=m-26880;  w=20;  st=64;  hw=320;   }
    else                { lvl=4; pos=m-27200;  w=10;  st=128; hw=80;    }
}

// ---- 1. decode scores + per-batch smem histogram ----
__global__ __launch_bounds__(256) void k_decode(Ptrs P){
    __shared__ int sh[HBINS];
    int b = blockIdx.y;
    for (int i = threadIdx.x; i < HBINS; i += 256) sh[i] = 0;
    __syncthreads();
    int base = blockIdx.x * 2048;
    #pragma unroll
    for (int r = 0; r < 8; r++){
        int n = base + r*256 + threadIdx.x;
        if (n < NPB){
            int mod = (n >= NPM) ? 1 : 0;
            int m   = n - mod*NPM;
            int lvl,pos,w,st,hw; locate(m,lvl,pos,w,st,hw);
            const float* __restrict__ cls = P.p[mod*15 + lvl];
            const float* __restrict__ cnt = P.p[mod*15 + 5 + lvl];
            int cbase = b*NCLS*hw + pos;
            float lm = cls[cbase];
            #pragma unroll
            for (int c=1;c<NCLS;c++) lm = fmaxf(lm, cls[cbase + c*hw]);
            float pmax = sigm(lm);                 // max_c sigm == sigm(max_c)
            float q = sigm(cnt[b*hw + pos]);
            float score = __fsqrt_rn(__fmul_rn(pmax, q));
            unsigned int sb = __float_as_uint(score);
            g_scores[b*NPB + n] = sb;
            atomicAdd(&sh[score_bin(sb)], 1);
        }
    }
    __syncthreads();
    for (int i = threadIdx.x; i < HBINS; i += 256){
        int v = sh[i];
        if (v) atomicAdd(&g_hist[b*HBINS + i], v);
    }
}

// ---- 2. per-batch bin threshold ----
__global__ void k_thresh(){
    int b = blockIdx.x;
    __shared__ int gsum[256];
    const int* h = &g_hist[b*HBINS];
    int s = 0;
    #pragma unroll 8
    for (int k = 0; k < 32; k++) s += h[threadIdx.x*32 + k];
    gsum[threadIdx.x] = s;
    __syncthreads();
    if (threadIdx.x == 0){
        int acc = 0, g = 255;
        while (g > 0 && acc + gsum[g] < MAXD){ acc += gsum[g]; g--; }
        int T = g*32;
        for (int k = 31; k >= 0; k--){
            acc += h[g*32 + k];
            if (acc >= MAXD){ T = g*32 + k; break; }
        }
        g_thr[b] = T;
    }
}

// ---- 3. compact candidates; also re-zero g_hist for next run ----
__global__ void k_compact(){
    int lid = (blockIdx.y*gridDim.x + blockIdx.x)*256 + threadIdx.x;
    if (lid < NB*HBINS) g_hist[lid] = 0;
    int n = blockIdx.x*256 + threadIdx.x;
    if (n >= NPB) return;
    int b = blockIdx.y;
    unsigned int sb = g_scores[b*NPB + n];
    if (score_bin(sb) >= g_thr[b]){
        int slot = atomicAdd(&g_ccount[b], 1);
        if (slot < CAP)
            g_cand[b*CAP + slot] =
                ((u64)sb << 28) | (u64)(0x0FFFFFFFu - (unsigned)n);
    }
}

// ---- 4. rank by enumeration (keys unique), early-exiting dead blocks ----
__global__ __launch_bounds__(256) void k_rank(){
    int b = blockIdx.y;
    int C = min(g_ccount[b], CAP);
    if (blockIdx.x*256 >= C) return;
    int idx = blockIdx.x*256 + threadIdx.x;
    u64 my = (idx < C) ? g_cand[b*CAP + idx] : 0ull;
    int rank = 0;
    __shared__ u64 tile[256];
    for (int t0 = 0; t0 < C; t0 += 256){
        int j = t0 + threadIdx.x;
        tile[threadIdx.x] = (j < C) ? g_cand[b*CAP + j] : 0ull;
        __syncthreads();
        int tn = min(256, C - t0);
        #pragma unroll 8
        for (int k = 0; k < tn; k++) rank += (tile[k] > my) ? 1 : 0;
        __syncthreads();
    }
    if (idx < C && rank < MAXD) g_topkeys[b*MAXD + rank] = my;
}

// ---- 5. fused gather + per-batch maxc + class-offset/area ----
__global__ __launch_bounds__(512) void k_gather_maxoff(Ptrs P){
    int b = blockIdx.x, tid = threadIdx.x;
    if (tid == 0) g_ccount[b] = 0;          // reset for next run
    __shared__ float red[512];
    __shared__ float s_mc1;
    float bx[2][4]; int cl[2];
    float mx = -INFINITY;
    #pragma unroll
    for (int q = 0; q < 2; q++){
        int j = q*512 + tid;
        cl[q] = 0;
        if (j < MAXD){
            int t = b*MAXD + j;
            u64 key = g_topkeys[t];
            float score = __uint_as_float((unsigned int)(key >> 28));
            int n = 0x0FFFFFFF - (int)(key & 0x0FFFFFFFull);
            int mod = (n >= NPM) ? 1 : 0;
            int m = n - mod*NPM;
            int lvl,pos,w,st,hw; locate(m,lvl,pos,w,st,hw);
            const float* cls = P.p[mod*15 + lvl];
            const float* reg = P.p[mod*15 + 10 + lvl];
            int cbase = b*NCLS*hw + pos;
            float best = sigm(cls[cbase]); int bi = 0;   // argmax in sigmoid space
            #pragma unroll
            for (int c=1;c<NCLS;c++){ float s = sigm(cls[cbase + c*hw]); if (s > best){best=s;bi=c;} }
            int y = pos / w, x = pos - y*w;
            float fx = (float)(x*st + (st>>1));
            float fy = (float)(y*st + (st>>1));
            int rbase = b*4*hw + pos;
            float r0=reg[rbase], r1=reg[rbase+hw], r2=reg[rbase+2*hw], r3=reg[rbase+3*hw];
            bx[q][0] = __fsub_rn(fx, r0);
            bx[q][1] = __fsub_rn(fy, r1);
            bx[q][2] = __fadd_rn(fx, r2);
            bx[q][3] = __fadd_rn(fy, r3);
            cl[q] = bi + 1;
            unsigned char vl = (score >= 0.05f) ? 1 : 0;
            g_top_s[t] = score;
            g_top_c[t] = cl[q];
            g_top_b[4*t+0]=bx[q][0]; g_top_b[4*t+1]=bx[q][1];
            g_top_b[4*t+2]=bx[q][2]; g_top_b[4*t+3]=bx[q][3];
            g_valid[t] = vl;
            if (vl) mx = fmaxf(mx, fmaxf(fmaxf(bx[q][0],bx[q][1]), fmaxf(bx[q][2],bx[q][3])));
            else    mx = fmaxf(mx, 0.0f);
        }
    }
    red[tid] = mx; __syncthreads();
    for (int s = 256; s > 0; s >>= 1){
        if (tid < s) red[tid] = fmaxf(red[tid], red[tid+s]);
        __syncthreads();
    }
    if (tid == 0) s_mc1 = __fadd_rn(red[0], 1.0f);
    __syncthreads();
    float mc1 = s_mc1;
    #pragma unroll
    for (int q = 0; q < 2; q++){
        int j = q*512 + tid;
        if (j < MAXD){
            int t = b*MAXD + j;
            float off = __fmul_rn((float)cl[q], mc1);
            float x1 = __fadd_rn(bx[q][0], off);
            float y1 = __fadd_rn(bx[q][1], off);
            float x2 = __fadd_rn(bx[q][2], off);
            float y2 = __fadd_rn(bx[q][3], off);
            g_ob[4*t+0]=x1; g_ob[4*t+1]=y1; g_ob[4*t+2]=x2; g_ob[4*t+3]=y2;
            g_area[t] = __fmul_rn(__fadd_rn(__fsub_rn(x2,x1),1.0f),
                                  __fadd_rn(__fsub_rn(y2,y1),1.0f));
        }
    }
}

// ---- 6. IoU > 0.6 bitmask: division-free EXACT test, upper triangle ----
__global__ __launch_bounds__(256) void k_mask(){
    int xt = blockIdx.x;                       // i tile (64 rows)
    int yg = blockIdx.y;                       // j group (4 words = 256 cols)
    if (4*yg + 3 < xt) return;
    int b  = blockIdx.z;
    __shared__ float sx1[256],sy1[256],sx2[256],sy2[256],sa[256];
    int jj = yg*256 + threadIdx.x;
    if (jj < MAXD){
        int tj = b*MAXD + jj;
        sx1[threadIdx.x]=g_ob[4*tj];   sy1[threadIdx.x]=g_ob[4*tj+1];
        sx2[threadIdx.x]=g_ob[4*tj+2]; sy2[threadIdx.x]=g_ob[4*tj+3];
        sa[threadIdx.x]=g_area[tj];
    }
    __syncthreads();
    int il = threadIdx.x & 63;
    int wq = threadIdx.x >> 6;
    int i  = xt*64 + il;
    int w  = yg*4 + wq;
    if (i >= MAXD) return;
    if (w < (i >> 6)) return;
    int j0 = w*64;
    int jn = min(64, MAXD - j0);
    if (jn <= 0) return;
    int ti = b*MAXD + i;
    float x1=g_ob[4*ti], y1=g_ob[4*ti+1], x2=g_ob[4*ti+2], y2=g_ob[4*ti+3], ai=g_area[ti];
    int sb = wq*64;
    u64 word = 0;
    for (int k=0;k<jn;k++){
        float xx1=fmaxf(x1,sx1[sb+k]), yy1=fmaxf(y1,sy1[sb+k]);
        float xx2=fminf(x2,sx2[sb+k]), yy2=fminf(y2,sy2[sb+k]);
        float iw=fmaxf(__fadd_rn(__fsub_rn(xx2,xx1),1.0f),0.0f);
        float ih=fmaxf(__fadd_rn(__fsub_rn(yy2,yy1),1.0f),0.0f);
        float inter=__fmul_rn(iw,ih);
        float denom=__fsub_rn(__fadd_rn(ai,sa[sb+k]),inter);
        // fl(inter/denom) > 0.6f, computed exactly without dividing:
        //   denom>0 : inter > MID*denom  (MID*denom exact in fp64: 25+24 bits)
        //   denom==0: inter>0 -> +inf > 0.6 -> suppress ; 0/0=NaN -> no
        //   denom<0 : quotient <= 0 (or NaN->no) -> never suppress
        bool sup;
        if (denom > 0.0f)       sup = ((double)inter > IOU_MID*(double)denom);
        else                    sup = (denom == 0.0f && inter > 0.0f);
        if (sup) word |= (1ull<<k);
    }
    g_mask[((size_t)b*NPAD + i)*MASKW + w] = word;
}

// ---- 7. fused greedy scan + output write (1 block per batch) ----
__global__ void k_scan_out(float* __restrict__ out){
    extern __shared__ u64 sm[];                    // NPAD*MASKW words
    __shared__ u64 svm[MASKW];
    __shared__ u64 skeep[MASKW];
    int b = blockIdx.x, tid = threadIdx.x;
    const u64* src = &g_mask[(size_t)b*NPAD*MASKW];
    for (int i = tid; i < NPAD*MASKW; i += blockDim.x)
        sm[i] = (i < MAXD*MASKW) ? src[i] : 0ull;
    if (tid < MASKW){
        u64 w = 0;
        for (int i = 0; i < 64; i++){
            int j = tid*64 + i;
            if (j < MAXD && g_valid[b*MAXD + j]) w |= 1ull << i;
        }
        svm[tid] = w;
    }
    __syncthreads();
    if (tid < 32){
        int lane = tid;
        u64 removed = 0;
        for (int c = 0; c < MASKW; c++){
            u64 sup = __shfl_sync(0xffffffffu, removed, c);
            u64 vmc = svm[c];
            u64 kd = 0;
            #pragma unroll
            for (int q = 0; q < 4; q++){
                u64 dreg[16];
                #pragma unroll
                for (int r = 0; r < 16; r++) dreg[r] = sm[(c*64 + q*16 + r)*MASKW + c];
                #pragma unroll
                for (int r = 0; r < 16; r++){
                    int i = q*16 + r;
                    bool k = ((vmc >> i) & 1ull) && !((sup >> i) & 1ull);
                    if (k){ kd |= 1ull << i; sup |= dreg[r]; }
                }
            }
            if (lane == c) skeep[c] = kd;
            if (lane < MASKW){
                #pragma unroll
                for (int i = 0; i < 64; i++)
                    if ((kd >> i) & 1ull)
                        removed |= sm[(size_t)(c*64 + i)*MASKW + lane];
            }
        }
    }
    __syncthreads();
    for (int j = tid; j < MAXD; j += blockDim.x){
        int t = b*MAXD + j;
        int keep = (int)((skeep[j >> 6] >> (j & 63)) & 1ull);
        float kf = keep ? 1.0f : 0.0f;
        out[t]        = __fmul_rn(g_top_s[t], kf);
        out[TOPN + t] = keep ? (float)g_top_c[t] : 0.0f;
        float x1 = fminf(fmaxf(g_top_b[4*t+0],0.0f),1279.0f);
        float y1 = fminf(fmaxf(g_top_b[4*t+1],0.0f),1023.0f);
        float x2 = fminf(fmaxf(g_top_b[4*t+2],0.0f),1279.0f);
        float y2 = fminf(fmaxf(g_top_b[4*t+3],0.0f),1023.0f);
        out[2*TOPN + 4*t+0]=__fmul_rn(x1,kf);
        out[2*TOPN + 4*t+1]=__fmul_rn(y1,kf);
        out[2*TOPN + 4*t+2]=__fmul_rn(x2,kf);
        out[2*TOPN + 4*t+3]=__fmul_rn(y2,kf);
        out[6*TOPN + t]=kf;
    }
}

extern "C" void kernel_launch(void* const* d_in, const int* in_sizes, int n_in,
                              void* d_out, int out_size){
    Ptrs P;
    for (int i=0;i<30;i++) P.p[i] = (const float*)d_in[i];

    const int scan_smem = NPAD*MASKW*8;   // 131072 bytes
    cudaFuncSetAttribute(k_scan_out, cudaFuncAttributeMaxDynamicSharedMemorySize, scan_smem);

    k_decode       <<<dim3((NPB + 2047)/2048, NB), 256>>>(P);
    k_thresh       <<<NB, 256>>>();
    k_compact      <<<dim3((NPB + 255)/256, NB), 256>>>();
    k_rank         <<<dim3(CAP/256, NB), 256>>>();
    k_gather_maxoff<<<NB, 512>>>(P);
    k_mask         <<<dim3(NPAD/64, 4, NB), 256>>>();
    k_scan_out     <<<NB, 256, scan_smem>>>((float*)d_out);
}

// round 10
// speedup vs baseline: 1.7513x; 1.7513x over previous
#include <cuda_runtime.h>

#define NB     16
#define NCLS   20
#define NPM    27280          // anchors per modality (div by 4)
#define NPB    (2*NPM)        // 54560 anchors per batch
#define NGRP   (NPB/4)        // 13640 anchor-groups per batch
#define TOTAL  (NB*NPB)       // 872960
#define MAXD   1000
#define NPAD   1024           // padded detections (16 x 64)
#define MASKW  16             // 1024 bits -> 16 u64 words
#define TOPN   (NB*MAXD)      // 16000
#define HBINS  8192
#define BINOFF 121856         // (0x3F800000>>13) - 8192
#define CAP    4096           // candidate capacity per batch (fine bins -> C~1100)

typedef unsigned long long u64;

struct Ptrs { const float* p[30]; };

// ---- static device scratch (no allocations; statics zero-init) ----
__device__ unsigned int g_scores[TOTAL];
__device__ int          g_hist[NB*HBINS];     // re-zeroed inside k_compact each run
__device__ int          g_thr[NB];
__device__ int          g_ccount[NB];         // re-zeroed inside k_gather_maxoff
__device__ u64          g_cand[NB*CAP];
__device__ u64          g_topkeys[TOPN];
__device__ float        g_top_s[TOPN];
__device__ int          g_top_c[TOPN];
__device__ float        g_top_b[TOPN*4];
__device__ unsigned char g_valid[TOPN];
__device__ float        g_ob[TOPN*4];
__device__ float        g_area[TOPN];
__device__ u64          g_mask[(size_t)NB*NPAD*MASKW];

// sigmoid exactly as passing rounds (rel_err 1.3e-8) — do not change
__device__ __forceinline__ float sigm(float x){
    return __fdiv_rn(1.0f, __fadd_rn(1.0f, expf(-x)));
}

// monotone fine-grained score binning (1024 bins across [0.5,1))
__device__ __forceinline__ int score_bin(unsigned int bits){
    int v = (int)(bits >> 13) - BINOFF;
    return max(0, min(HBINS-1, v));
}

__device__ __forceinline__ void locate(int m, int& lvl, int& pos, int& w, int& st, int& hw){
    if (m < 20480)      { lvl=0; pos=m;        w=160; st=8;   hw=20480; }
    else if (m < 25600) { lvl=1; pos=m-20480;  w=80;  st=16;  hw=5120;  }
    else if (m < 26880) { lvl=2; pos=m-25600;  w=40;  st=32;  hw=1280;  }
    else if (m < 27200) { lvl=3; pos=m-26880;  w=20;  st=64;  hw=320;   }
    else                { lvl=4; pos=m-27200;  w=10;  st=128; hw=80;    }
}

// ---- 1. decode (float4: 4 anchors/thread) + per-batch smem histogram ----
__global__ __launch_bounds__(256) void k_decode(Ptrs P){
    __shared__ int sh[HBINS];
    int b = blockIdx.y;
    for (int i = threadIdx.x; i < HBINS; i += 256) sh[i] = 0;
    __syncthreads();
    int g = blockIdx.x*256 + threadIdx.x;
    if (g < NGRP){
        int n = g*4;                                   // 4 anchors, same modality+level
        int mod = (n >= NPM) ? 1 : 0;
        int m   = n - mod*NPM;
        int lvl,pos,w,st,hw; locate(m,lvl,pos,w,st,hw);
        const float4* __restrict__ cls4 = (const float4*)P.p[mod*15 + lvl];
        const float4* __restrict__ cnt4 = (const float4*)P.p[mod*15 + 5 + lvl];
        int hw4 = hw >> 2, p4 = pos >> 2;
        int cbase = b*NCLS*hw4 + p4;
        float4 lm = cls4[cbase];
        #pragma unroll
        for (int c=1;c<NCLS;c++){
            float4 v = cls4[cbase + c*hw4];
            lm.x = fmaxf(lm.x, v.x); lm.y = fmaxf(lm.y, v.y);
            lm.z = fmaxf(lm.z, v.z); lm.w = fmaxf(lm.w, v.w);
        }
        float4 qv = cnt4[b*hw4 + p4];
        float lmv[4] = {lm.x, lm.y, lm.z, lm.w};
        float qvv[4] = {qv.x, qv.y, qv.z, qv.w};
        unsigned int sb[4];
        #pragma unroll
        for (int j=0;j<4;j++){
            float pmax = sigm(lmv[j]);                 // max_c sigm == sigm(max_c)
            float q = sigm(qvv[j]);
            float score = __fsqrt_rn(__fmul_rn(pmax, q));
            sb[j] = __float_as_uint(score);
            atomicAdd(&sh[score_bin(sb[j])], 1);
        }
        *(uint4*)&g_scores[b*NPB + n] = make_uint4(sb[0],sb[1],sb[2],sb[3]);
    }
    __syncthreads();
    for (int i = threadIdx.x; i < HBINS; i += 256){
        int v = sh[i];
        if (v) atomicAdd(&g_hist[b*HBINS + i], v);
    }
}

// ---- 2. per-batch bin threshold ----
__global__ void k_thresh(){
    int b = blockIdx.x;
    __shared__ int gsum[256];
    const int* h = &g_hist[b*HBINS];
    int s = 0;
    #pragma unroll 8
    for (int k = 0; k < 32; k++) s += h[threadIdx.x*32 + k];
    gsum[threadIdx.x] = s;
    __syncthreads();
    if (threadIdx.x == 0){
        int acc = 0, g = 255;
        while (g > 0 && acc + gsum[g] < MAXD){ acc += gsum[g]; g--; }
        int T = g*32;
        for (int k = 31; k >= 0; k--){
            acc += h[g*32 + k];
            if (acc >= MAXD){ T = g*32 + k; break; }
        }
        g_thr[b] = T;
    }
}

// ---- 3. compact candidates; also re-zero g_hist for next run ----
__global__ void k_compact(){
    int lid = (blockIdx.y*gridDim.x + blockIdx.x)*256 + threadIdx.x;
    if (lid < NB*HBINS) g_hist[lid] = 0;
    int n = blockIdx.x*256 + threadIdx.x;
    if (n >= NPB) return;
    int b = blockIdx.y;
    unsigned int sb = g_scores[b*NPB + n];
    if (score_bin(sb) >= g_thr[b]){
        int slot = atomicAdd(&g_ccount[b], 1);
        if (slot < CAP)
            g_cand[b*CAP + slot] =
                ((u64)sb << 28) | (u64)(0x0FFFFFFFu - (unsigned)n);
    }
}

// ---- 4. rank by enumeration (keys unique), early-exiting dead blocks ----
__global__ __launch_bounds__(256) void k_rank(){
    int b = blockIdx.y;
    int C = min(g_ccount[b], CAP);
    if (blockIdx.x*256 >= C) return;
    int idx = blockIdx.x*256 + threadIdx.x;
    u64 my = (idx < C) ? g_cand[b*CAP + idx] : 0ull;
    int rank = 0;
    __shared__ u64 tile[256];
    for (int t0 = 0; t0 < C; t0 += 256){
        int j = t0 + threadIdx.x;
        tile[threadIdx.x] = (j < C) ? g_cand[b*CAP + j] : 0ull;
        __syncthreads();
        int tn = min(256, C - t0);
        #pragma unroll 8
        for (int k = 0; k < tn; k++) rank += (tile[k] > my) ? 1 : 0;
        __syncthreads();
    }
    if (idx < C && rank < MAXD) g_topkeys[b*MAXD + rank] = my;
}

// ---- 5. fused gather + per-batch maxc + class-offset/area ----
__global__ __launch_bounds__(512) void k_gather_maxoff(Ptrs P){
    int b = blockIdx.x, tid = threadIdx.x;
    if (tid == 0) g_ccount[b] = 0;          // reset for next run
    __shared__ float red[512];
    __shared__ float s_mc1;
    float bx[2][4]; int cl[2];
    float mx = -INFINITY;
    #pragma unroll
    for (int q = 0; q < 2; q++){
        int j = q*512 + tid;
        cl[q] = 0;
        if (j < MAXD){
            int t = b*MAXD + j;
            u64 key = g_topkeys[t];
            float score = __uint_as_float((unsigned int)(key >> 28));
            int n = 0x0FFFFFFF - (int)(key & 0x0FFFFFFFull);
            int mod = (n >= NPM) ? 1 : 0;
            int m = n - mod*NPM;
            int lvl,pos,w,st,hw; locate(m,lvl,pos,w,st,hw);
            const float* cls = P.p[mod*15 + lvl];
            const float* reg = P.p[mod*15 + 10 + lvl];
            int cbase = b*NCLS*hw + pos;
            float best = sigm(cls[cbase]); int bi = 0;   // argmax in sigmoid space
            #pragma unroll
            for (int c=1;c<NCLS;c++){ float s = sigm(cls[cbase + c*hw]); if (s > best){best=s;bi=c;} }
            int y = pos / w, x = pos - y*w;
            float fx = (float)(x*st + (st>>1));
            float fy = (float)(y*st + (st>>1));
            int rbase = b*4*hw + pos;
            float r0=reg[rbase], r1=reg[rbase+hw], r2=reg[rbase+2*hw], r3=reg[rbase+3*hw];
            bx[q][0] = __fsub_rn(fx, r0);
            bx[q][1] = __fsub_rn(fy, r1);
            bx[q][2] = __fadd_rn(fx, r2);
            bx[q][3] = __fadd_rn(fy, r3);
            cl[q] = bi + 1;
            unsigned char vl = (score >= 0.05f) ? 1 : 0;
            g_top_s[t] = score;
            g_top_c[t] = cl[q];
            g_top_b[4*t+0]=bx[q][0]; g_top_b[4*t+1]=bx[q][1];
            g_top_b[4*t+2]=bx[q][2]; g_top_b[4*t+3]=bx[q][3];
            g_valid[t] = vl;
            if (vl) mx = fmaxf(mx, fmaxf(fmaxf(bx[q][0],bx[q][1]), fmaxf(bx[q][2],bx[q][3])));
            else    mx = fmaxf(mx, 0.0f);
        }
    }
    red[tid] = mx; __syncthreads();
    for (int s = 256; s > 0; s >>= 1){
        if (tid < s) red[tid] = fmaxf(red[tid], red[tid+s]);
        __syncthreads();
    }
    if (tid == 0) s_mc1 = __fadd_rn(red[0], 1.0f);
    __syncthreads();
    float mc1 = s_mc1;
    #pragma unroll
    for (int q = 0; q < 2; q++){
        int j = q*512 + tid;
        if (j < MAXD){
            int t = b*MAXD + j;
            float off = __fmul_rn((float)cl[q], mc1);
            float x1 = __fadd_rn(bx[q][0], off);
            float y1 = __fadd_rn(bx[q][1], off);
            float x2 = __fadd_rn(bx[q][2], off);
            float y2 = __fadd_rn(bx[q][3], off);
            g_ob[4*t+0]=x1; g_ob[4*t+1]=y1; g_ob[4*t+2]=x2; g_ob[4*t+3]=y2;
            g_area[t] = __fmul_rn(__fadd_rn(__fsub_rn(x2,x1),1.0f),
                                  __fadd_rn(__fsub_rn(y2,y1),1.0f));
        }
    }
}

// ---- 6. IoU > 0.6 bitmask: fp32-only EXACT division-free test, upper triangle ----
// fl(inter/denom) > 0.6f  <=>  inter > (0.6f + 2^-25)*denom  (denom>0; RNE ties fail '>')
// Two-product: p=0.6f*d, e=fma(0.6f,d,-p) exact; s=e+2^-25*d; t=inter-p (Sterbenz near
// boundary, sign-dominant away). Decision identical to fdiv except measure-zero cases
// (quotient within ~2^-48 of the midpoint; P ~ 3e-8 per run).
__global__ __launch_bounds__(256) void k_mask(){
    int xt = blockIdx.x;                       // i tile (64 rows)
    int yg = blockIdx.y;                       // j group (4 words = 256 cols)
    if (4*yg + 3 < xt) return;
    int b  = blockIdx.z;
    __shared__ float sx1[256],sy1[256],sx2[256],sy2[256],sa[256];
    int jj = yg*256 + threadIdx.x;
    if (jj < MAXD){
        int tj = b*MAXD + jj;
        sx1[threadIdx.x]=g_ob[4*tj];   sy1[threadIdx.x]=g_ob[4*tj+1];
        sx2[threadIdx.x]=g_ob[4*tj+2]; sy2[threadIdx.x]=g_ob[4*tj+3];
        sa[threadIdx.x]=g_area[tj];
    }
    __syncthreads();
    int il = threadIdx.x & 63;
    int wq = threadIdx.x >> 6;
    int i  = xt*64 + il;
    int w  = yg*4 + wq;
    if (i >= MAXD) return;
    if (w < (i >> 6)) return;
    int j0 = w*64;
    int jn = min(64, MAXD - j0);
    if (jn <= 0) return;
    int ti = b*MAXD + i;
    float x1=g_ob[4*ti], y1=g_ob[4*ti+1], x2=g_ob[4*ti+2], y2=g_ob[4*ti+3], ai=g_area[ti];
    int sb = wq*64;
    u64 word = 0;
    for (int k=0;k<jn;k++){
        float xx1=fmaxf(x1,sx1[sb+k]), yy1=fmaxf(y1,sy1[sb+k]);
        float xx2=fminf(x2,sx2[sb+k]), yy2=fminf(y2,sy2[sb+k]);
        float iw=fmaxf(__fadd_rn(__fsub_rn(xx2,xx1),1.0f),0.0f);
        float ih=fmaxf(__fadd_rn(__fsub_rn(yy2,yy1),1.0f),0.0f);
        float inter=__fmul_rn(iw,ih);
        float denom=__fsub_rn(__fadd_rn(ai,sa[sb+k]),inter);
        float p = __fmul_rn(0.6f, denom);
        float e = __fmaf_rn(0.6f, denom, -p);                  // exact residual
        float s = __fadd_rn(e, __fmul_rn(0x1.0p-25f, denom));  // half-ulp shift
        float t = __fsub_rn(inter, p);
        bool sup;
        if (denom > 0.0f) sup = (t > s);
        else              sup = (denom == 0.0f && inter > 0.0f);
        if (sup) word |= (1ull<<k);
    }
    g_mask[((size_t)b*NPAD + i)*MASKW + w] = word;
}

// ---- 7. fused greedy scan + output write (1 block per batch) ----
__global__ void k_scan_out(float* __restrict__ out){
    extern __shared__ u64 sm[];                    // NPAD*MASKW words
    __shared__ u64 svm[MASKW];
    __shared__ u64 skeep[MASKW];
    int b = blockIdx.x, tid = threadIdx.x;
    const u64* src = &g_mask[(size_t)b*NPAD*MASKW];
    for (int i = tid; i < NPAD*MASKW; i += blockDim.x)
        sm[i] = (i < MAXD*MASKW) ? src[i] : 0ull;
    if (tid < MASKW){
        u64 w = 0;
        for (int i = 0; i < 64; i++){
            int j = tid*64 + i;
            if (j < MAXD && g_valid[b*MAXD + j]) w |= 1ull << i;
        }
        svm[tid] = w;
    }
    __syncthreads();
    if (tid < 32){
        int lane = tid;
        u64 removed = 0;
        for (int c = 0; c < MASKW; c++){
            u64 sup = __shfl_sync(0xffffffffu, removed, c);
            u64 vmc = svm[c];
            u64 kd = 0;
            #pragma unroll
            for (int q = 0; q < 4; q++){
                u64 dreg[16];
                #pragma unroll
                for (int r = 0; r < 16; r++) dreg[r] = sm[(c*64 + q*16 + r)*MASKW + c];
                #pragma unroll
                for (int r = 0; r < 16; r++){
                    int i = q*16 + r;
                    bool k = ((vmc >> i) & 1ull) && !((sup >> i) & 1ull);
                    if (k){ kd |= 1ull << i; sup |= dreg[r]; }
                }
            }
            if (lane == c) skeep[c] = kd;
            if (lane < MASKW){
                #pragma unroll
                for (int i = 0; i < 64; i++)
                    if ((kd >> i) & 1ull)
                        removed |= sm[(size_t)(c*64 + i)*MASKW + lane];
            }
        }
    }
    __syncthreads();
    for (int j = tid; j < MAXD; j += blockDim.x){
        int t = b*MAXD + j;
        int keep = (int)((skeep[j >> 6] >> (j & 63)) & 1ull);
        float kf = keep ? 1.0f : 0.0f;
        out[t]        = __fmul_rn(g_top_s[t], kf);
        out[TOPN + t] = keep ? (float)g_top_c[t] : 0.0f;
        float x1 = fminf(fmaxf(g_top_b[4*t+0],0.0f),1279.0f);
        float y1 = fminf(fmaxf(g_top_b[4*t+1],0.0f),1023.0f);
        float x2 = fminf(fmaxf(g_top_b[4*t+2],0.0f),1279.0f);
        float y2 = fminf(fmaxf(g_top_b[4*t+3],0.0f),1023.0f);
        out[2*TOPN + 4*t+0]=__fmul_rn(x1,kf);
        out[2*TOPN + 4*t+1]=__fmul_rn(y1,kf);
        out[2*TOPN + 4*t+2]=__fmul_rn(x2,kf);
        out[2*TOPN + 4*t+3]=__fmul_rn(y2,kf);
        out[6*TOPN + t]=kf;
    }
}

extern "C" void kernel_launch(void* const* d_in, const int* in_sizes, int n_in,
                              void* d_out, int out_size){
    Ptrs P;
    for (int i=0;i<30;i++) P.p[i] = (const float*)d_in[i];

    const int scan_smem = NPAD*MASKW*8;   // 131072 bytes
    cudaFuncSetAttribute(k_scan_out, cudaFuncAttributeMaxDynamicSharedMemorySize, scan_smem);

    k_decode       <<<dim3((NGRP + 255)/256, NB), 256>>>(P);
    k_thresh       <<<NB, 256>>>();
    k_compact      <<<dim3((NPB + 255)/256, NB), 256>>>();
    k_rank         <<<dim3(CAP/256, NB), 256>>>();
    k_gather_maxoff<<<NB, 512>>>(P);
    k_mask         <<<dim3(NPAD/64, 4, NB), 256>>>();
    k_scan_out     <<<NB, 256, scan_smem>>>((float*)d_out);
}